// round 15
// baseline (speedup 1.0000x reference)
#include <cuda_runtime.h>
#include <math.h>
#include <stdint.h>
#include <limits.h>

// ---------------------------------------------------------------------------
// Quantizer: x [4,16,1024] f32, codebook [65536,16] f32.
// out[0:65536] = nearest codebook entry per token, [B,D,T]; out[65536] = loss.
//
// 4 launches:
//   prepA : per-block |.| maxima partials
//   prepB : reduce partials -> scales; quantize codebook; reset imax/loss
//   scan  : int8 dp4a scores; per-(token, 64-code tile) max -> INT16 table
//           in blocked layout [token_blk16][tile][16]; per-token int max via
//           atomicMax (deterministic)
//   finish: CTA-per-16-tokens; 32KB CONTIGUOUS table stream -> smem;
//           exact fp32 rescue within rigorous 2E; fused deterministic loss
// ---------------------------------------------------------------------------

#define TOKENS   4096
#define NCODES   65536
#define DIM      16
#define STC      64                  // codes per tile
#define NST      (NCODES / STC)      // 1024 tiles
#define TPC      4                   // tiles per scan CTA
#define NGR      (NST / TPC)         // 256 scan groups
#define PBLK     256
#define FT       16                  // tokens per finish CTA
#define FGRID    (TOKENS / FT)       // 256
#define ROWP     18                  // padded shorts per smem tile row
#define NINF     __int_as_float(0xff800000)
#define FULL     0xffffffffu
#define LSCALE   4294967296.0        // 2^32 fixed-point loss scale

__device__ float    g_part[PBLK * 4];
__device__ unsigned g_scal[4];            // maxX, maxC, SAc (float bits)
__device__ int4     g_Bq[NCODES];         // packed int8 codes, 1 MB
__device__ int      g_bias[NCODES];       // bias in int score units
__device__ short    g_tb16[(size_t)TOKENS * NST]; // blocked [tblk][tile][16], 8 MB
__device__ int      g_imax[TOKENS];       // per-token int score max
__device__ unsigned long long g_lsum;
__device__ unsigned g_cnt;

__device__ __forceinline__ void cpasync16(const void* dst_smem, const void* src) {
    unsigned s = (unsigned)__cvta_generic_to_shared(dst_smem);
    asm volatile("cp.async.cg.shared.global [%0], [%1], 16;" :: "r"(s), "l"(src));
}
#define CP_COMMIT() asm volatile("cp.async.commit_group;")
#define CP_WAIT0()  asm volatile("cp.async.wait_group 0;")

__device__ __forceinline__ int pack4(int a0, int a1, int a2, int a3) {
    return (a0 & 0xFF) | ((a1 & 0xFF) << 8) | ((a2 & 0xFF) << 16) | (a3 << 24);
}

// ---------------------------------------------------------------------------
// prepA: per-block maxima of |x|, max|c|, Sum|c| -> g_part.
// ---------------------------------------------------------------------------
__global__ __launch_bounds__(256) void prepA_kernel(const float* __restrict__ x,
                                                    const float* __restrict__ cb) {
    __shared__ float sm[3][256];
    int i = blockIdx.x * 256 + threadIdx.x;          // 0..65535
    float ax = fabsf(x[i]);
    const float4* c4 = (const float4*)(cb + (size_t)i * DIM);
    float mc = 0.0f, sa = 0.0f;
#pragma unroll
    for (int v = 0; v < 4; v++) {
        float4 q = c4[v];
        float a0 = fabsf(q.x), a1 = fabsf(q.y), a2 = fabsf(q.z), a3 = fabsf(q.w);
        mc = fmaxf(fmaxf(mc, fmaxf(a0, a1)), fmaxf(a2, a3));
        sa += a0; sa += a1; sa += a2; sa += a3;
    }
    sm[0][threadIdx.x] = ax; sm[1][threadIdx.x] = mc; sm[2][threadIdx.x] = sa;
    __syncthreads();
    for (int s = 128; s > 0; s >>= 1) {
        if (threadIdx.x < s) {
#pragma unroll
            for (int k = 0; k < 3; k++)
                sm[k][threadIdx.x] = fmaxf(sm[k][threadIdx.x], sm[k][threadIdx.x + s]);
        }
        __syncthreads();
    }
    if (threadIdx.x < 3) g_part[blockIdx.x * 4 + threadIdx.x] = sm[threadIdx.x][0];
}

// ---------------------------------------------------------------------------
// prepB: reduce partials, publish scales, quantize codebook, reset state.
// ---------------------------------------------------------------------------
__global__ __launch_bounds__(256) void prepB_kernel(const float* __restrict__ cb) {
    __shared__ float sm[3][256];
    const int tid = threadIdx.x;
    sm[0][tid] = g_part[tid * 4 + 0];
    sm[1][tid] = g_part[tid * 4 + 1];
    sm[2][tid] = g_part[tid * 4 + 2];
    __syncthreads();
    for (int s = 128; s > 0; s >>= 1) {
        if (tid < s) {
#pragma unroll
            for (int k = 0; k < 3; k++)
                sm[k][tid] = fmaxf(sm[k][tid], sm[k][tid + s]);
        }
        __syncthreads();
    }
    const float maxX = sm[0][0], maxC = sm[1][0], SAc = sm[2][0];
    int gidx = blockIdx.x * 256 + tid;
    if (gidx < TOKENS) g_imax[gidx] = INT_MIN;       // per-replay reset
    if (gidx == 0) {
        g_scal[0] = __float_as_uint(maxX);
        g_scal[1] = __float_as_uint(maxC);
        g_scal[2] = __float_as_uint(SAc);
        g_lsum = 0ull;
        g_cnt  = 0u;
    }

    const float sx = maxX * (1.0f / 127.0f);
    const float sc = maxC * (1.0f / 127.0f);
    const float qc = 127.0f / maxC;
    const float4* c4 = (const float4*)(cb + (size_t)gidx * DIM);
    int q[DIM];
    float h = 0.0f;
#pragma unroll
    for (int v = 0; v < 4; v++) {
        float4 p = c4[v];
        h = fmaf(p.x, p.x, h); q[v * 4 + 0] = __float2int_rn(p.x * qc);
        h = fmaf(p.y, p.y, h); q[v * 4 + 1] = __float2int_rn(p.y * qc);
        h = fmaf(p.z, p.z, h); q[v * 4 + 2] = __float2int_rn(p.z * qc);
        h = fmaf(p.w, p.w, h); q[v * 4 + 3] = __float2int_rn(p.w * qc);
    }
    int4 w;
    w.x = pack4(q[0], q[1], q[2], q[3]);
    w.y = pack4(q[4], q[5], q[6], q[7]);
    w.z = pack4(q[8], q[9], q[10], q[11]);
    w.w = pack4(q[12], q[13], q[14], q[15]);
    g_Bq[gidx] = w;
    g_bias[gidx] = __float2int_rn(-0.5f * h / (sx * sc));
}

// ---------------------------------------------------------------------------
// scan: int8 dp4a (R11 body). grid (4, 256), 256 thr, 4 tokens/thread,
// 4 tiles/CTA, 4 CTAs/SM. Adds: atomicMax per-token imax; int16 blocked
// table store:  addr = (token>>4)*NST*16 + tile*16 + (token&15).
// ---------------------------------------------------------------------------
__global__ __launch_bounds__(256, 4) void scan_kernel(const float* __restrict__ x) {
    __shared__ int4 sQ[TPC * STC];     // 4 KB
    __shared__ int  sB[TPC * STC];     // 1 KB

    const int tid = threadIdx.x;
    const int batch = blockIdx.x;              // 0..3
    const int grp = blockIdx.y;                // 0..255
    const int c0 = grp * (TPC * STC);

    cpasync16(&sQ[tid], &g_Bq[c0 + tid]);
    if (tid < 64) cpasync16(&sB[tid * 4], &g_bias[c0 + tid * 4]);
    CP_COMMIT();

    const float maxX = __uint_as_float(g_scal[0]);
    const float qx = 127.0f / maxX;

    const float* xp = x + (size_t)batch * (DIM * 1024);
    int xq[4][4];
#pragma unroll
    for (int tk = 0; tk < 4; tk++) {
        int t = tk * 256 + tid;
#pragma unroll
        for (int w = 0; w < 4; w++) {
            int q0 = __float2int_rn(xp[(w * 4 + 0) * 1024 + t] * qx);
            int q1 = __float2int_rn(xp[(w * 4 + 1) * 1024 + t] * qx);
            int q2 = __float2int_rn(xp[(w * 4 + 2) * 1024 + t] * qx);
            int q3 = __float2int_rn(xp[(w * 4 + 3) * 1024 + t] * qx);
            xq[tk][w] = pack4(q0, q1, q2, q3);
        }
    }

    CP_WAIT0();
    __syncthreads();

    const int4* b4 = (const int4*)sB;
    int tmax[4];
#pragma unroll
    for (int tk = 0; tk < 4; tk++) tmax[tk] = INT_MIN;

#pragma unroll
    for (int st = 0; st < TPC; st++) {
        int m[4];
#pragma unroll
        for (int tk = 0; tk < 4; tk++) m[tk] = INT_MIN;
#pragma unroll 4
        for (int g = 0; g < STC / 4; g++) {
            int4 bb = b4[st * (STC / 4) + g];
            int bias[4] = {bb.x, bb.y, bb.z, bb.w};
#pragma unroll
            for (int u = 0; u < 4; u++) {
                int4 q = sQ[st * STC + g * 4 + u];
#pragma unroll
                for (int tk = 0; tk < 4; tk++) {
                    int a = __dp4a(q.x, xq[tk][0], bias[u]);
                    a = __dp4a(q.y, xq[tk][1], a);
                    a = __dp4a(q.z, xq[tk][2], a);
                    a = __dp4a(q.w, xq[tk][3], a);
                    m[tk] = max(m[tk], a);
                }
            }
        }
        const int tile = grp * TPC + st;
#pragma unroll
        for (int tk = 0; tk < 4; tk++) {
            int token = batch * 1024 + tk * 256 + tid;
            // round-UP quantization keeps admission conservative
            short v16 = (short)((m[tk] + 31) >> 5);
            g_tb16[(size_t)(token >> 4) * (NST * 16) + tile * 16 + (token & 15)] = v16;
            tmax[tk] = max(tmax[tk], m[tk]);
        }
    }

#pragma unroll
    for (int tk = 0; tk < 4; tk++)
        atomicMax(&g_imax[batch * 1024 + tk * 256 + tid], tmax[tk]);
}

// ---------------------------------------------------------------------------
// finish: CTA per 16 tokens (grid 256). 32 KB CONTIGUOUS table stream ->
// smem (pad 18: conflict-free); warp per 2 tokens; exact rescue; fused loss.
// ---------------------------------------------------------------------------
__global__ __launch_bounds__(256) void finish_kernel(const float* __restrict__ x,
                                                     const float* __restrict__ cb,
                                                     float* __restrict__ out,
                                                     int out_size) {
    __shared__ short tbs[NST][ROWP];     // 1024 x 18 shorts = 36 KB
    __shared__ float sh_err[8];

    const int tid  = threadIdx.x;
    const int lane = tid & 31;
    const int warp = tid >> 5;
    const int t0   = blockIdx.x * FT;

    // contiguous bulk stream: 32768 B; 8 int4 per thread, coalesced
    {
        const int4* src = (const int4*)(g_tb16 + (size_t)blockIdx.x * (NST * 16));
#pragma unroll
        for (int i = 0; i < 8; i++) {
            int idx = i * 256 + tid;          // 0..2047
            int4 v = src[idx];
            int tile = idx >> 1, half = idx & 1;
            int* dst = (int*)&tbs[tile][half * 8];   // 4-byte aligned
            dst[0] = v.x; dst[1] = v.y; dst[2] = v.z; dst[3] = v.w;
        }
    }
    __syncthreads();

    const float maxX = __uint_as_float(g_scal[0]);
    const float maxC = __uint_as_float(g_scal[1]);
    const float SAc  = __uint_as_float(g_scal[2]);
    const float sx = maxX * (1.0f / 127.0f);
    const float sc = maxC * (1.0f / 127.0f);
    const float s  = sx * sc;

    float werr = 0.0f;

#pragma unroll
    for (int jj = 0; jj < 2; jj++) {
        const int j = warp * 2 + jj;         // 0..15
        const int token = t0 + j;
        const int bb = token >> 10, t = token & 1023;

        float xr[DIM];
        float SAx = 0.0f;
#pragma unroll
        for (int d = 0; d < DIM; d++) {
            xr[d] = x[(size_t)bb * (DIM * 1024) + d * 1024 + t];
            SAx += fabsf(xr[d]);
        }

        const int imax = g_imax[token];
        const float E = 0.5f * sc * SAx + 0.5f * sx * SAc
                      + 16.0f * sx * sc + sx * sc + 1e-2f;
        const int thr16 = (imax - (int)ceilf(2.0f * E / s)) >> 5;  // round down

        // candidate mask: bit k -> tile k*32+lane (banks lane*9 mod 32: distinct)
        unsigned cmask = 0u;
#pragma unroll
        for (int k = 0; k < 32; k++)
            if ((int)tbs[k * 32 + lane][j] >= thr16) cmask |= (1u << k);

        float best = NINF;
        int   bi   = 0x7fffffff;

        unsigned act = __ballot_sync(FULL, cmask != 0u);
        while (act) {
            int w = __ffs(act) - 1;
            act &= act - 1;
            unsigned msk = __shfl_sync(FULL, cmask, w);
            while (msk) {
                int k = __ffs(msk) - 1;
                msk &= msk - 1;
                int cbase = (k * 32 + w) * STC;
#pragma unroll
                for (int half = 0; half < 2; half++) {
                    int c = cbase + half * 32 + lane;
                    const float4* cr = (const float4*)(cb + (size_t)c * DIM);
                    float acc = 0.0f, h = 0.0f;
#pragma unroll
                    for (int v4 = 0; v4 < 4; v4++) {
                        float4 q = cr[v4];
                        acc = fmaf(q.x, xr[v4 * 4 + 0], acc); h = fmaf(q.x, q.x, h);
                        acc = fmaf(q.y, xr[v4 * 4 + 1], acc); h = fmaf(q.y, q.y, h);
                        acc = fmaf(q.z, xr[v4 * 4 + 2], acc); h = fmaf(q.z, q.z, h);
                        acc = fmaf(q.w, xr[v4 * 4 + 3], acc); h = fmaf(q.w, q.w, h);
                    }
                    float sscore = acc - 0.5f * h;
                    if (sscore > best || (sscore == best && c < bi)) {
                        best = sscore; bi = c;   // order-free first-index-wins
                    }
                }
            }
        }

#pragma unroll
        for (int off = 16; off > 0; off >>= 1) {
            float vb = __shfl_xor_sync(FULL, best, off);
            int   ib = __shfl_xor_sync(FULL, bi,   off);
            if (vb > best || (vb == best && ib < bi)) { best = vb; bi = ib; }
        }

        float e = 0.0f;
        if (lane < DIM) {
            float qd = cb[(size_t)bi * DIM + lane];
            float df = qd - xr[lane];
            e = df * df;
            out[(size_t)bb * (DIM * 1024) + lane * 1024 + t] = qd;
        }
#pragma unroll
        for (int off = 16; off > 0; off >>= 1)
            e += __shfl_xor_sync(FULL, e, off);
        werr += e;
    }

    if (lane == 0) sh_err[warp] = werr;
    __syncthreads();
    if (tid == 0) {
        float ce = 0.0f;
#pragma unroll
        for (int w = 0; w < 8; w++) ce += sh_err[w];    // fixed order
        unsigned long long r =
            (unsigned long long)__double2ll_rn((double)ce * LSCALE);
        atomicAdd(&g_lsum, r);
        __threadfence();
        unsigned ticket = atomicAdd(&g_cnt, 1u);
        if (ticket == FGRID - 1 && out_size > NCODES) {
            double sum = (double)*(volatile unsigned long long*)&g_lsum;
            out[NCODES] = (float)(sum / LSCALE / (double)(TOKENS * DIM));
        }
    }
}

// ---------------------------------------------------------------------------
extern "C" void kernel_launch(void* const* d_in, const int* in_sizes, int n_in,
                              void* d_out, int out_size) {
    const float* x  = (const float*)d_in[0];   // [4,16,1024]
    const float* cb = (const float*)d_in[1];   // [65536,16]
    float* out = (float*)d_out;

    prepA_kernel<<<PBLK, 256>>>(x, cb);
    prepB_kernel<<<NCODES / 256, 256>>>(cb);

    dim3 grid(4, NGR);
    scan_kernel<<<grid, 256>>>(x);

    finish_kernel<<<FGRID, 256>>>(x, cb, out, out_size);
}

// round 16
// speedup vs baseline: 1.6302x; 1.6302x over previous
#include <cuda_runtime.h>
#include <math.h>
#include <stdint.h>
#include <limits.h>

// ---------------------------------------------------------------------------
// Quantizer: x [4,16,1024] f32, codebook [65536,16] f32.
// out[0:65536] = nearest codebook entry per token, [B,D,T]; out[65536] = loss.
//
// 4 launches:
//   prepA : global maxima partials; reset per-tile norm maxima
//   prepB : scales; quantize codebook; per-code -0.5||c||^2 (fp32) ;
//           per-tile max ||c||, ||rc|| (atomicMax, deterministic); resets
//   scan  : int8 dp4a tile maxima; CERTIFIED per-tile bounds:
//             ub = m + E_tile  -> int16 blocked table
//             lb = m - E_tile  -> per-token atomicMax
//           E_tile = ||rx||*Mc_t + (||x||+||rx||)*Mr_t  (norm-exact)
//   finish: grid (256 tokblk x 4 tile-quarters); pure-compare admission;
//           exact fp32 rescue; packed-key atomicMax winner; last-quarter
//           ticket gathers + fused deterministic fixed-point loss
// ---------------------------------------------------------------------------

#define TOKENS   4096
#define NCODES   65536
#define DIM      16
#define STC      64                  // codes per tile
#define NST      (NCODES / STC)      // 1024 tiles
#define TPC      4                   // tiles per scan CTA
#define NGR      (NST / TPC)         // 256 scan groups
#define PBLK     256
#define TBLK     256                 // finish token blocks (16 tokens each)
#define QT       4                   // tile quarters
#define QTILES   (NST / QT)          // 256 tiles per quarter
#define NINF     __int_as_float(0xff800000)
#define FULL     0xffffffffu
#define LSCALE   4294967296.0        // 2^32 fixed-point loss scale

__device__ float    g_part[PBLK * 4];
__device__ unsigned g_scal[4];            // maxX, maxC (float bits)
__device__ int4     g_Bq[NCODES];         // packed int8 codes, 1 MB
__device__ int      g_bias[NCODES];       // bias in int score units
__device__ float    g_biasf[NCODES];      // exact fp32 -0.5||c||^2
__device__ unsigned g_Mc[NST];            // per-tile max ||c||   (float bits)
__device__ unsigned g_Mr[NST];            // per-tile max ||rc||  (float bits)
__device__ short    g_tb16[(size_t)TOKENS * NST]; // blocked [tblk][tile][16], 8MB
__device__ int      g_lb[TOKENS];         // per-token certified lower bound
__device__ unsigned long long g_best[TOKENS]; // packed (scoreOrd, ~idx)
__device__ unsigned g_qcnt[TBLK];         // per-block quarter tickets
__device__ unsigned long long g_lsum;
__device__ unsigned g_cnt;

__device__ __forceinline__ void cpasync16(const void* dst_smem, const void* src) {
    unsigned s = (unsigned)__cvta_generic_to_shared(dst_smem);
    asm volatile("cp.async.cg.shared.global [%0], [%1], 16;" :: "r"(s), "l"(src));
}
#define CP_COMMIT() asm volatile("cp.async.commit_group;")
#define CP_WAIT0()  asm volatile("cp.async.wait_group 0;")

__device__ __forceinline__ int pack4(int a0, int a1, int a2, int a3) {
    return (a0 & 0xFF) | ((a1 & 0xFF) << 8) | ((a2 & 0xFF) << 16) | (a3 << 24);
}

// ---------------------------------------------------------------------------
// prepA: per-block maxima of |x|, max|c| -> g_part; reset tile-norm maxima.
// ---------------------------------------------------------------------------
__global__ __launch_bounds__(256) void prepA_kernel(const float* __restrict__ x,
                                                    const float* __restrict__ cb) {
    __shared__ float sm[2][256];
    int i = blockIdx.x * 256 + threadIdx.x;          // 0..65535
    if (i < NST) { g_Mc[i] = 0u; g_Mr[i] = 0u; }     // reset (used next launch)
    float ax = fabsf(x[i]);
    const float4* c4 = (const float4*)(cb + (size_t)i * DIM);
    float mc = 0.0f;
#pragma unroll
    for (int v = 0; v < 4; v++) {
        float4 q = c4[v];
        mc = fmaxf(mc, fmaxf(fmaxf(fabsf(q.x), fabsf(q.y)),
                             fmaxf(fabsf(q.z), fabsf(q.w))));
    }
    sm[0][threadIdx.x] = ax; sm[1][threadIdx.x] = mc;
    __syncthreads();
    for (int s = 128; s > 0; s >>= 1) {
        if (threadIdx.x < s) {
            sm[0][threadIdx.x] = fmaxf(sm[0][threadIdx.x], sm[0][threadIdx.x + s]);
            sm[1][threadIdx.x] = fmaxf(sm[1][threadIdx.x], sm[1][threadIdx.x + s]);
        }
        __syncthreads();
    }
    if (threadIdx.x < 2) g_part[blockIdx.x * 4 + threadIdx.x] = sm[threadIdx.x][0];
}

// ---------------------------------------------------------------------------
// prepB: scales; quantize codebook; fp32 bias; per-tile norm maxima; resets.
// ---------------------------------------------------------------------------
__global__ __launch_bounds__(256) void prepB_kernel(const float* __restrict__ cb) {
    __shared__ float sm[2][256];
    const int tid = threadIdx.x;
    sm[0][tid] = g_part[tid * 4 + 0];
    sm[1][tid] = g_part[tid * 4 + 1];
    __syncthreads();
    for (int s = 128; s > 0; s >>= 1) {
        if (tid < s) {
            sm[0][tid] = fmaxf(sm[0][tid], sm[0][tid + s]);
            sm[1][tid] = fmaxf(sm[1][tid], sm[1][tid + s]);
        }
        __syncthreads();
    }
    const float maxX = sm[0][0], maxC = sm[1][0];
    int gidx = blockIdx.x * 256 + tid;
    if (gidx < TOKENS) {                      // per-replay reset
        g_lb[gidx] = INT_MIN;
        g_best[gidx] = 0ull;
    }
    if (gidx < TBLK) g_qcnt[gidx] = 0u;
    if (gidx == 0) {
        g_scal[0] = __float_as_uint(maxX);
        g_scal[1] = __float_as_uint(maxC);
        g_lsum = 0ull;
        g_cnt  = 0u;
    }

    const float sx = maxX * (1.0f / 127.0f);
    const float sc = maxC * (1.0f / 127.0f);
    const float qc = 127.0f / maxC;
    const float4* c4 = (const float4*)(cb + (size_t)gidx * DIM);
    float cf[DIM];
    int q[DIM];
    float h = 0.0f;
#pragma unroll
    for (int v = 0; v < 4; v++) {
        float4 p = c4[v];
        cf[v*4+0] = p.x; cf[v*4+1] = p.y; cf[v*4+2] = p.z; cf[v*4+3] = p.w;
        h = fmaf(p.x, p.x, h); q[v*4+0] = __float2int_rn(p.x * qc);
        h = fmaf(p.y, p.y, h); q[v*4+1] = __float2int_rn(p.y * qc);
        h = fmaf(p.z, p.z, h); q[v*4+2] = __float2int_rn(p.z * qc);
        h = fmaf(p.w, p.w, h); q[v*4+3] = __float2int_rn(p.w * qc);
    }
    int4 w;
    w.x = pack4(q[0], q[1], q[2], q[3]);
    w.y = pack4(q[4], q[5], q[6], q[7]);
    w.z = pack4(q[8], q[9], q[10], q[11]);
    w.w = pack4(q[12], q[13], q[14], q[15]);
    g_Bq[gidx] = w;
    g_bias[gidx]  = __float2int_rn(-0.5f * h / (sx * sc));
    g_biasf[gidx] = -0.5f * h;                 // matches rescue arithmetic

    // per-code ||c|| and quantization-residual norm ||rc||
    float rn2 = 0.0f;
#pragma unroll
    for (int d = 0; d < DIM; d++) {
        float r = cf[d] - sc * (float)q[d];
        rn2 = fmaf(r, r, rn2);
    }
    float cnorm = sqrtf(h)   * 1.000001f;      // conservative inflation
    float rnorm = sqrtf(rn2) * 1.000001f;
    atomicMax(&g_Mc[gidx >> 6], __float_as_uint(cnorm));
    atomicMax(&g_Mr[gidx >> 6], __float_as_uint(rnorm));
}

// ---------------------------------------------------------------------------
// scan: int8 dp4a. grid (4, 256), 256 thr, 4 tokens/thread, 4 tiles/CTA.
// Stores certified UPPER bounds (int16 blocked); atomicMax certified LOWER
// bound per token.
// ---------------------------------------------------------------------------
__global__ __launch_bounds__(256, 4) void scan_kernel(const float* __restrict__ x) {
    __shared__ int4  sQ[TPC * STC];     // 4 KB
    __shared__ int   sB[TPC * STC];     // 1 KB

    const int tid = threadIdx.x;
    const int batch = blockIdx.x;              // 0..3
    const int grp = blockIdx.y;                // 0..255
    const int c0 = grp * (TPC * STC);

    cpasync16(&sQ[tid], &g_Bq[c0 + tid]);
    if (tid < 64) cpasync16(&sB[tid * 4], &g_bias[c0 + tid * 4]);
    CP_COMMIT();

    const float maxX = __uint_as_float(g_scal[0]);
    const float maxC = __uint_as_float(g_scal[1]);
    const float sx = maxX * (1.0f / 127.0f);
    const float sc = maxC * (1.0f / 127.0f);
    const float s  = sx * sc;
    const float inv_s = 1.0f / s;
    const float qx = 127.0f / maxX;

    // per-tile norms for this CTA's 4 tiles
    float Mc[TPC], Mr[TPC];
#pragma unroll
    for (int st = 0; st < TPC; st++) {
        Mc[st] = __uint_as_float(g_Mc[grp * TPC + st]);
        Mr[st] = __uint_as_float(g_Mr[grp * TPC + st]);
    }

    // quantize 4 tokens; exact ||x||, ||rx|| per token
    const float* xp = x + (size_t)batch * (DIM * 1024);
    int   xq[4][4];
    float xn[4], rxn[4];
#pragma unroll
    for (int tk = 0; tk < 4; tk++) {
        int t = tk * 256 + tid;
        float xn2 = 0.0f, rn2 = 0.0f;
        int qd[DIM];
#pragma unroll
        for (int d = 0; d < DIM; d++) {
            float f = xp[d * 1024 + t];
            qd[d] = __float2int_rn(f * qx);
            float r = f - sx * (float)qd[d];
            xn2 = fmaf(f, f, xn2);
            rn2 = fmaf(r, r, rn2);
        }
#pragma unroll
        for (int w = 0; w < 4; w++)
            xq[tk][w] = pack4(qd[w*4], qd[w*4+1], qd[w*4+2], qd[w*4+3]);
        xn[tk]  = sqrtf(xn2) * 1.000001f;
        rxn[tk] = sqrtf(rn2) * 1.000001f;
    }

    CP_WAIT0();
    __syncthreads();

    const int4* b4 = (const int4*)sB;
    int lbmax[4];
#pragma unroll
    for (int tk = 0; tk < 4; tk++) lbmax[tk] = INT_MIN;

#pragma unroll
    for (int st = 0; st < TPC; st++) {
        int m[4];
#pragma unroll
        for (int tk = 0; tk < 4; tk++) m[tk] = INT_MIN;
#pragma unroll 4
        for (int g = 0; g < STC / 4; g++) {
            int4 bb = b4[st * (STC / 4) + g];
            int bias[4] = {bb.x, bb.y, bb.z, bb.w};
#pragma unroll
            for (int u = 0; u < 4; u++) {
                int4 q = sQ[st * STC + g * 4 + u];
#pragma unroll
                for (int tk = 0; tk < 4; tk++) {
                    int a = __dp4a(q.x, xq[tk][0], bias[u]);
                    a = __dp4a(q.y, xq[tk][1], a);
                    a = __dp4a(q.z, xq[tk][2], a);
                    a = __dp4a(q.w, xq[tk][3], a);
                    m[tk] = max(m[tk], a);
                }
            }
        }
        const int tile = grp * TPC + st;
#pragma unroll
        for (int tk = 0; tk < 4; tk++) {
            // E_tile = ||rx||*Mc + (||x||+||rx||)*Mr  (+ slack for bias/int)
            float Ef = rxn[tk] * Mc[st] + (xn[tk] + rxn[tk]) * Mr[st];
            int Ei = (int)ceilf(Ef * inv_s) + 2;
            int token = batch * 1024 + tk * 256 + tid;
            short ub16 = (short)((m[tk] + Ei + 31) >> 5);   // round UP
            g_tb16[(size_t)(token >> 4) * (NST * 16) + tile * 16 + (token & 15)] = ub16;
            lbmax[tk] = max(lbmax[tk], m[tk] - Ei);
        }
    }

#pragma unroll
    for (int tk = 0; tk < 4; tk++)
        atomicMax(&g_lb[batch * 1024 + tk * 256 + tid], lbmax[tk]);
}

// ---------------------------------------------------------------------------
// finish: grid (256 token-blocks, 4 quarters), 256 thr, 9 KB smem.
// Pure-compare admission; exact rescue; packed-key winner; ticket gather.
// ---------------------------------------------------------------------------
__global__ __launch_bounds__(256) void finish_kernel(const float* __restrict__ x,
                                                     const float* __restrict__ cb,
                                                     float* __restrict__ out,
                                                     int out_size) {
    __shared__ short tbs[QTILES][18];    // 256 tiles x 16 tokens (pad 18) = 9 KB
    __shared__ float shf[256];
    __shared__ int   sflag;

    const int tid  = threadIdx.x;
    const int lane = tid & 31;
    const int warp = tid >> 5;
    const int tblk = blockIdx.x;         // 0..255
    const int qt   = blockIdx.y;         // 0..3
    const int tile0 = qt * QTILES;

    // contiguous 8 KB sub-block load (512 int4)
    {
        const int4* src = (const int4*)(g_tb16 + (size_t)tblk * (NST * 16)
                                        + (size_t)tile0 * 16);
#pragma unroll
        for (int i = 0; i < 2; i++) {
            int idx = i * 256 + tid;          // 0..511
            int4 v = src[idx];
            int tile = idx >> 1, half = idx & 1;
            int* dst = (int*)&tbs[tile][half * 8];
            dst[0] = v.x; dst[1] = v.y; dst[2] = v.z; dst[3] = v.w;
        }
    }
    __syncthreads();

#pragma unroll
    for (int jj = 0; jj < 2; jj++) {
        const int j = warp * 2 + jj;         // 0..15
        const int token = tblk * 16 + j;
        const int bb = token >> 10, t = token & 1023;

        float xr[DIM];
#pragma unroll
        for (int d = 0; d < DIM; d++)
            xr[d] = x[(size_t)bb * (DIM * 1024) + d * 1024 + t];

        const int thr16 = g_lb[token] >> 5;   // floor(lb/32), arithmetic

        // candidate mask: bit k -> local tile k*32+lane
        unsigned cmask = 0u;
#pragma unroll
        for (int k = 0; k < 8; k++)
            if ((int)tbs[k * 32 + lane][j] >= thr16) cmask |= (1u << k);

        float best = NINF;
        int   bi   = 0x7fffffff;

        unsigned act = __ballot_sync(FULL, cmask != 0u);
        while (act) {
            int w = __ffs(act) - 1;
            act &= act - 1;
            unsigned msk = __shfl_sync(FULL, cmask, w);
            while (msk) {
                int k = __ffs(msk) - 1;
                msk &= msk - 1;
                int cbase = (tile0 + k * 32 + w) * STC;
#pragma unroll
                for (int half = 0; half < 2; half++) {
                    int c = cbase + half * 32 + lane;
                    const float4* cr = (const float4*)(cb + (size_t)c * DIM);
                    float acc = 0.0f;
#pragma unroll
                    for (int v4 = 0; v4 < 4; v4++) {
                        float4 q = cr[v4];
                        acc = fmaf(q.x, xr[v4 * 4 + 0], acc);
                        acc = fmaf(q.y, xr[v4 * 4 + 1], acc);
                        acc = fmaf(q.z, xr[v4 * 4 + 2], acc);
                        acc = fmaf(q.w, xr[v4 * 4 + 3], acc);
                    }
                    float sscore = acc + g_biasf[c];   // == acc - 0.5h bitwise
                    if (sscore > best || (sscore == best && c < bi)) {
                        best = sscore; bi = c;   // order-free first-index-wins
                    }
                }
            }
        }

#pragma unroll
        for (int off = 16; off > 0; off >>= 1) {
            float vb = __shfl_xor_sync(FULL, best, off);
            int   ib = __shfl_xor_sync(FULL, bi,   off);
            if (vb > best || (vb == best && ib < bi)) { best = vb; bi = ib; }
        }

        if (lane == 0 && bi != 0x7fffffff) {
            unsigned so = __float_as_uint(best);
            so = (so & 0x80000000u) ? ~so : (so | 0x80000000u);
            unsigned long long key = ((unsigned long long)so << 32) | (unsigned)(~bi);
            atomicMax(&g_best[token], key);      // max score, ties -> min idx
        }
    }

    // quarter ticket: last of 4 gathers the 16 tokens + loss
    __syncthreads();
    if (tid == 0) {
        __threadfence();
        unsigned tk = atomicAdd(&g_qcnt[tblk], 1u);
        sflag = (tk == QT - 1);
    }
    __syncthreads();
    if (!sflag) return;

    {
        int j = tid >> 4, d = tid & 15;                 // 256 = 16 tok x 16 dim
        int token = tblk * 16 + j;
        int bb = token >> 10, t = token & 1023;
        unsigned long long key = *(volatile unsigned long long*)&g_best[token];
        int code = (int)(~(unsigned)key);
        float qd = cb[(size_t)code * DIM + d];
        float xd = x[(size_t)bb * (DIM * 1024) + d * 1024 + t];
        out[(size_t)bb * (DIM * 1024) + d * 1024 + t] = qd;
        float df = qd - xd;
        shf[tid] = df * df;
    }
    __syncthreads();
    for (int s = 128; s > 0; s >>= 1) {
        if (tid < s) shf[tid] += shf[tid + s];
        __syncthreads();
    }
    if (tid == 0) {
        unsigned long long r =
            (unsigned long long)__double2ll_rn((double)shf[0] * LSCALE);
        atomicAdd(&g_lsum, r);
        __threadfence();
        unsigned ticket = atomicAdd(&g_cnt, 1u);
        if (ticket == TBLK - 1 && out_size > NCODES) {
            double sum = (double)*(volatile unsigned long long*)&g_lsum;
            out[NCODES] = (float)(sum / LSCALE / (double)(TOKENS * DIM));
        }
    }
}

// ---------------------------------------------------------------------------
extern "C" void kernel_launch(void* const* d_in, const int* in_sizes, int n_in,
                              void* d_out, int out_size) {
    const float* x  = (const float*)d_in[0];   // [4,16,1024]
    const float* cb = (const float*)d_in[1];   // [65536,16]
    float* out = (float*)d_out;

    prepA_kernel<<<PBLK, 256>>>(x, cb);
    prepB_kernel<<<NCODES / 256, 256>>>(cb);

    dim3 sgrid(4, NGR);
    scan_kernel<<<sgrid, 256>>>(x);

    dim3 fgrid(TBLK, QT);
    finish_kernel<<<fgrid, 256>>>(x, cb, out, out_size);
}

// round 17
// speedup vs baseline: 1.6664x; 1.0222x over previous
#include <cuda_runtime.h>
#include <math.h>
#include <stdint.h>
#include <limits.h>

// ---------------------------------------------------------------------------
// Quantizer: x [4,16,1024] f32, codebook [65536,16] f32.
// out[0:65536] = nearest codebook entry per token, [B,D,T]; out[65536] = loss.
//
// 4 launches:
//   prepA : global maxima partials; reset per-tile norm maxima
//   prepB : scales; quantize codebook; fp32 bias; per-tile max ||c||,||rc||
//   scan  : int8 dp4a tile maxima; certified per-tile bounds:
//             ub = m + E_tile -> int16 blocked table
//             lb = m - E_tile -> per-token atomicMax
//   finish: grid (256 tokblk x 8 tile-eighths) = 2048 CTAs (~14/SM);
//           pure-compare admission; exact fp32 rescue; packed-key winner;
//           last-eighth ticket gathers + fused deterministic loss
// ---------------------------------------------------------------------------

#define TOKENS   4096
#define NCODES   65536
#define DIM      16
#define STC      64                  // codes per tile
#define NST      (NCODES / STC)      // 1024 tiles
#define TPC      4                   // tiles per scan CTA
#define NGR      (NST / TPC)         // 256 scan groups
#define PBLK     256
#define TBLK     256                 // finish token blocks (16 tokens each)
#define QT       8                   // tile slices per token block
#define QTILES   (NST / QT)          // 128 tiles per slice
#define NINF     __int_as_float(0xff800000)
#define FULL     0xffffffffu
#define LSCALE   4294967296.0        // 2^32 fixed-point loss scale

__device__ float    g_part[PBLK * 4];
__device__ unsigned g_scal[4];            // maxX, maxC (float bits)
__device__ int4     g_Bq[NCODES];         // packed int8 codes, 1 MB
__device__ int      g_bias[NCODES];       // bias in int score units
__device__ float    g_biasf[NCODES];      // exact fp32 -0.5||c||^2
__device__ unsigned g_Mc[NST];            // per-tile max ||c||   (float bits)
__device__ unsigned g_Mr[NST];            // per-tile max ||rc||  (float bits)
__device__ short    g_tb16[(size_t)TOKENS * NST]; // blocked [tblk][tile][16], 8MB
__device__ int      g_lb[TOKENS];         // per-token certified lower bound
__device__ unsigned long long g_best[TOKENS]; // packed (scoreOrd, ~idx)
__device__ unsigned g_qcnt[TBLK];         // per-block slice tickets
__device__ unsigned long long g_lsum;
__device__ unsigned g_cnt;

__device__ __forceinline__ void cpasync16(const void* dst_smem, const void* src) {
    unsigned s = (unsigned)__cvta_generic_to_shared(dst_smem);
    asm volatile("cp.async.cg.shared.global [%0], [%1], 16;" :: "r"(s), "l"(src));
}
#define CP_COMMIT() asm volatile("cp.async.commit_group;")
#define CP_WAIT0()  asm volatile("cp.async.wait_group 0;")

__device__ __forceinline__ int pack4(int a0, int a1, int a2, int a3) {
    return (a0 & 0xFF) | ((a1 & 0xFF) << 8) | ((a2 & 0xFF) << 16) | (a3 << 24);
}

// ---------------------------------------------------------------------------
// prepA: per-block maxima of |x|, max|c| -> g_part; reset tile-norm maxima.
// ---------------------------------------------------------------------------
__global__ __launch_bounds__(256) void prepA_kernel(const float* __restrict__ x,
                                                    const float* __restrict__ cb) {
    __shared__ float sm[2][256];
    int i = blockIdx.x * 256 + threadIdx.x;          // 0..65535
    if (i < NST) { g_Mc[i] = 0u; g_Mr[i] = 0u; }     // reset (used next launch)
    float ax = fabsf(x[i]);
    const float4* c4 = (const float4*)(cb + (size_t)i * DIM);
    float mc = 0.0f;
#pragma unroll
    for (int v = 0; v < 4; v++) {
        float4 q = c4[v];
        mc = fmaxf(mc, fmaxf(fmaxf(fabsf(q.x), fabsf(q.y)),
                             fmaxf(fabsf(q.z), fabsf(q.w))));
    }
    sm[0][threadIdx.x] = ax; sm[1][threadIdx.x] = mc;
    __syncthreads();
    for (int s = 128; s > 0; s >>= 1) {
        if (threadIdx.x < s) {
            sm[0][threadIdx.x] = fmaxf(sm[0][threadIdx.x], sm[0][threadIdx.x + s]);
            sm[1][threadIdx.x] = fmaxf(sm[1][threadIdx.x], sm[1][threadIdx.x + s]);
        }
        __syncthreads();
    }
    if (threadIdx.x < 2) g_part[blockIdx.x * 4 + threadIdx.x] = sm[threadIdx.x][0];
}

// ---------------------------------------------------------------------------
// prepB: scales; quantize codebook; fp32 bias; per-tile norm maxima; resets.
// ---------------------------------------------------------------------------
__global__ __launch_bounds__(256) void prepB_kernel(const float* __restrict__ cb) {
    __shared__ float sm[2][256];
    const int tid = threadIdx.x;
    sm[0][tid] = g_part[tid * 4 + 0];
    sm[1][tid] = g_part[tid * 4 + 1];
    __syncthreads();
    for (int s = 128; s > 0; s >>= 1) {
        if (tid < s) {
            sm[0][tid] = fmaxf(sm[0][tid], sm[0][tid + s]);
            sm[1][tid] = fmaxf(sm[1][tid], sm[1][tid + s]);
        }
        __syncthreads();
    }
    const float maxX = sm[0][0], maxC = sm[1][0];
    int gidx = blockIdx.x * 256 + tid;
    if (gidx < TOKENS) {                      // per-replay reset
        g_lb[gidx] = INT_MIN;
        g_best[gidx] = 0ull;
    }
    if (gidx < TBLK) g_qcnt[gidx] = 0u;
    if (gidx == 0) {
        g_scal[0] = __float_as_uint(maxX);
        g_scal[1] = __float_as_uint(maxC);
        g_lsum = 0ull;
        g_cnt  = 0u;
    }

    const float sx = maxX * (1.0f / 127.0f);
    const float sc = maxC * (1.0f / 127.0f);
    const float qc = 127.0f / maxC;
    const float4* c4 = (const float4*)(cb + (size_t)gidx * DIM);
    float cf[DIM];
    int q[DIM];
    float h = 0.0f;
#pragma unroll
    for (int v = 0; v < 4; v++) {
        float4 p = c4[v];
        cf[v*4+0] = p.x; cf[v*4+1] = p.y; cf[v*4+2] = p.z; cf[v*4+3] = p.w;
        h = fmaf(p.x, p.x, h); q[v*4+0] = __float2int_rn(p.x * qc);
        h = fmaf(p.y, p.y, h); q[v*4+1] = __float2int_rn(p.y * qc);
        h = fmaf(p.z, p.z, h); q[v*4+2] = __float2int_rn(p.z * qc);
        h = fmaf(p.w, p.w, h); q[v*4+3] = __float2int_rn(p.w * qc);
    }
    int4 w;
    w.x = pack4(q[0], q[1], q[2], q[3]);
    w.y = pack4(q[4], q[5], q[6], q[7]);
    w.z = pack4(q[8], q[9], q[10], q[11]);
    w.w = pack4(q[12], q[13], q[14], q[15]);
    g_Bq[gidx] = w;
    g_bias[gidx]  = __float2int_rn(-0.5f * h / (sx * sc));
    g_biasf[gidx] = -0.5f * h;                 // matches rescue arithmetic

    float rn2 = 0.0f;
#pragma unroll
    for (int d = 0; d < DIM; d++) {
        float r = cf[d] - sc * (float)q[d];
        rn2 = fmaf(r, r, rn2);
    }
    float cnorm = sqrtf(h)   * 1.000001f;      // conservative inflation
    float rnorm = sqrtf(rn2) * 1.000001f;
    atomicMax(&g_Mc[gidx >> 6], __float_as_uint(cnorm));
    atomicMax(&g_Mr[gidx >> 6], __float_as_uint(rnorm));
}

// ---------------------------------------------------------------------------
// scan: int8 dp4a. grid (4, 256), 256 thr, 4 tokens/thread, 4 tiles/CTA.
// Certified UPPER bounds -> int16 blocked table; LOWER bound -> atomicMax.
// ---------------------------------------------------------------------------
__global__ __launch_bounds__(256, 4) void scan_kernel(const float* __restrict__ x) {
    __shared__ int4  sQ[TPC * STC];     // 4 KB
    __shared__ int   sB[TPC * STC];     // 1 KB

    const int tid = threadIdx.x;
    const int batch = blockIdx.x;              // 0..3
    const int grp = blockIdx.y;                // 0..255
    const int c0 = grp * (TPC * STC);

    cpasync16(&sQ[tid], &g_Bq[c0 + tid]);
    if (tid < 64) cpasync16(&sB[tid * 4], &g_bias[c0 + tid * 4]);
    CP_COMMIT();

    const float maxX = __uint_as_float(g_scal[0]);
    const float maxC = __uint_as_float(g_scal[1]);
    const float sx = maxX * (1.0f / 127.0f);
    const float sc = maxC * (1.0f / 127.0f);
    const float s  = sx * sc;
    const float inv_s = 1.0f / s;
    const float qx = 127.0f / maxX;

    float Mc[TPC], Mr[TPC];
#pragma unroll
    for (int st = 0; st < TPC; st++) {
        Mc[st] = __uint_as_float(g_Mc[grp * TPC + st]);
        Mr[st] = __uint_as_float(g_Mr[grp * TPC + st]);
    }

    const float* xp = x + (size_t)batch * (DIM * 1024);
    int   xq[4][4];
    float xn[4], rxn[4];
#pragma unroll
    for (int tk = 0; tk < 4; tk++) {
        int t = tk * 256 + tid;
        float xn2 = 0.0f, rn2 = 0.0f;
        int qd[DIM];
#pragma unroll
        for (int d = 0; d < DIM; d++) {
            float f = xp[d * 1024 + t];
            qd[d] = __float2int_rn(f * qx);
            float r = f - sx * (float)qd[d];
            xn2 = fmaf(f, f, xn2);
            rn2 = fmaf(r, r, rn2);
        }
#pragma unroll
        for (int w = 0; w < 4; w++)
            xq[tk][w] = pack4(qd[w*4], qd[w*4+1], qd[w*4+2], qd[w*4+3]);
        xn[tk]  = sqrtf(xn2) * 1.000001f;
        rxn[tk] = sqrtf(rn2) * 1.000001f;
    }

    CP_WAIT0();
    __syncthreads();

    const int4* b4 = (const int4*)sB;
    int lbmax[4];
#pragma unroll
    for (int tk = 0; tk < 4; tk++) lbmax[tk] = INT_MIN;

#pragma unroll
    for (int st = 0; st < TPC; st++) {
        int m[4];
#pragma unroll
        for (int tk = 0; tk < 4; tk++) m[tk] = INT_MIN;
#pragma unroll 4
        for (int g = 0; g < STC / 4; g++) {
            int4 bb = b4[st * (STC / 4) + g];
            int bias[4] = {bb.x, bb.y, bb.z, bb.w};
#pragma unroll
            for (int u = 0; u < 4; u++) {
                int4 q = sQ[st * STC + g * 4 + u];
#pragma unroll
                for (int tk = 0; tk < 4; tk++) {
                    int a = __dp4a(q.x, xq[tk][0], bias[u]);
                    a = __dp4a(q.y, xq[tk][1], a);
                    a = __dp4a(q.z, xq[tk][2], a);
                    a = __dp4a(q.w, xq[tk][3], a);
                    m[tk] = max(m[tk], a);
                }
            }
        }
        const int tile = grp * TPC + st;
#pragma unroll
        for (int tk = 0; tk < 4; tk++) {
            float Ef = rxn[tk] * Mc[st] + (xn[tk] + rxn[tk]) * Mr[st];
            int Ei = (int)ceilf(Ef * inv_s) + 2;
            int token = batch * 1024 + tk * 256 + tid;
            short ub16 = (short)((m[tk] + Ei + 31) >> 5);   // round UP
            g_tb16[(size_t)(token >> 4) * (NST * 16) + tile * 16 + (token & 15)] = ub16;
            lbmax[tk] = max(lbmax[tk], m[tk] - Ei);
        }
    }

#pragma unroll
    for (int tk = 0; tk < 4; tk++)
        atomicMax(&g_lb[batch * 1024 + tk * 256 + tid], lbmax[tk]);
}

// ---------------------------------------------------------------------------
// finish: grid (256 token-blocks, 8 slices) = 2048 CTAs (~14/SM), 256 thr,
// 4.6 KB smem. Pure-compare admission; exact rescue; packed-key winner.
// ---------------------------------------------------------------------------
__global__ __launch_bounds__(256) void finish_kernel(const float* __restrict__ x,
                                                     const float* __restrict__ cb,
                                                     float* __restrict__ out,
                                                     int out_size) {
    __shared__ short tbs[QTILES][18];    // 128 tiles x 16 tokens (pad 18) = 4.6 KB
    __shared__ float shf[256];
    __shared__ int   sflag;

    const int tid  = threadIdx.x;
    const int lane = tid & 31;
    const int warp = tid >> 5;
    const int tblk = blockIdx.x;         // 0..255
    const int qt   = blockIdx.y;         // 0..7
    const int tile0 = qt * QTILES;

    // contiguous 4 KB sub-block load (256 int4, one per thread)
    {
        const int4* src = (const int4*)(g_tb16 + (size_t)tblk * (NST * 16)
                                        + (size_t)tile0 * 16);
        int4 v = src[tid];
        int tile = tid >> 1, half = tid & 1;
        int* dst = (int*)&tbs[tile][half * 8];
        dst[0] = v.x; dst[1] = v.y; dst[2] = v.z; dst[3] = v.w;
    }
    __syncthreads();

#pragma unroll
    for (int jj = 0; jj < 2; jj++) {
        const int j = warp * 2 + jj;         // 0..15
        const int token = tblk * 16 + j;
        const int bb = token >> 10, t = token & 1023;

        float xr[DIM];
#pragma unroll
        for (int d = 0; d < DIM; d++)
            xr[d] = x[(size_t)bb * (DIM * 1024) + d * 1024 + t];

        const int thr16 = g_lb[token] >> 5;   // floor(lb/32), arithmetic

        // candidate mask: bit k -> local tile k*32+lane (k in 0..3)
        unsigned cmask = 0u;
#pragma unroll
        for (int k = 0; k < QTILES / 32; k++)
            if ((int)tbs[k * 32 + lane][j] >= thr16) cmask |= (1u << k);

        float best = NINF;
        int   bi   = 0x7fffffff;

        unsigned act = __ballot_sync(FULL, cmask != 0u);
        while (act) {
            int w = __ffs(act) - 1;
            act &= act - 1;
            unsigned msk = __shfl_sync(FULL, cmask, w);
            while (msk) {
                int k = __ffs(msk) - 1;
                msk &= msk - 1;
                int cbase = (tile0 + k * 32 + w) * STC;
#pragma unroll
                for (int half = 0; half < 2; half++) {
                    int c = cbase + half * 32 + lane;
                    const float4* cr = (const float4*)(cb + (size_t)c * DIM);
                    float acc = 0.0f;
#pragma unroll
                    for (int v4 = 0; v4 < 4; v4++) {
                        float4 q = cr[v4];
                        acc = fmaf(q.x, xr[v4 * 4 + 0], acc);
                        acc = fmaf(q.y, xr[v4 * 4 + 1], acc);
                        acc = fmaf(q.z, xr[v4 * 4 + 2], acc);
                        acc = fmaf(q.w, xr[v4 * 4 + 3], acc);
                    }
                    float sscore = acc + g_biasf[c];   // == acc - 0.5h bitwise
                    if (sscore > best || (sscore == best && c < bi)) {
                        best = sscore; bi = c;   // order-free first-index-wins
                    }
                }
            }
        }

#pragma unroll
        for (int off = 16; off > 0; off >>= 1) {
            float vb = __shfl_xor_sync(FULL, best, off);
            int   ib = __shfl_xor_sync(FULL, bi,   off);
            if (vb > best || (vb == best && ib < bi)) { best = vb; bi = ib; }
        }

        if (lane == 0 && bi != 0x7fffffff) {
            unsigned so = __float_as_uint(best);
            so = (so & 0x80000000u) ? ~so : (so | 0x80000000u);
            unsigned long long key = ((unsigned long long)so << 32) | (unsigned)(~bi);
            atomicMax(&g_best[token], key);      // max score, ties -> min idx
        }
    }

    // slice ticket: last of QT gathers the 16 tokens + loss
    __syncthreads();
    if (tid == 0) {
        __threadfence();
        unsigned tk = atomicAdd(&g_qcnt[tblk], 1u);
        sflag = (tk == QT - 1);
    }
    __syncthreads();
    if (!sflag) return;

    {
        int j = tid >> 4, d = tid & 15;                 // 256 = 16 tok x 16 dim
        int token = tblk * 16 + j;
        int bb = token >> 10, t = token & 1023;
        unsigned long long key = *(volatile unsigned long long*)&g_best[token];
        int code = (int)(~(unsigned)key);
        float qd = cb[(size_t)code * DIM + d];
        float xd = x[(size_t)bb * (DIM * 1024) + d * 1024 + t];
        out[(size_t)bb * (DIM * 1024) + d * 1024 + t] = qd;
        float df = qd - xd;
        shf[tid] = df * df;
    }
    __syncthreads();
    for (int s = 128; s > 0; s >>= 1) {
        if (tid < s) shf[tid] += shf[tid + s];
        __syncthreads();
    }
    if (tid == 0) {
        unsigned long long r =
            (unsigned long long)__double2ll_rn((double)shf[0] * LSCALE);
        atomicAdd(&g_lsum, r);
        __threadfence();
        unsigned ticket = atomicAdd(&g_cnt, 1u);
        if (ticket == TBLK - 1 && out_size > NCODES) {
            double sum = (double)*(volatile unsigned long long*)&g_lsum;
            out[NCODES] = (float)(sum / LSCALE / (double)(TOKENS * DIM));
        }
    }
}

// ---------------------------------------------------------------------------
extern "C" void kernel_launch(void* const* d_in, const int* in_sizes, int n_in,
                              void* d_out, int out_size) {
    const float* x  = (const float*)d_in[0];   // [4,16,1024]
    const float* cb = (const float*)d_in[1];   // [65536,16]
    float* out = (float*)d_out;

    prepA_kernel<<<PBLK, 256>>>(x, cb);
    prepB_kernel<<<NCODES / 256, 256>>>(cb);

    dim3 sgrid(4, NGR);
    scan_kernel<<<sgrid, 256>>>(x);

    dim3 fgrid(TBLK, QT);
    finish_kernel<<<fgrid, 256>>>(x, cb, out, out_size);
}